// round 1
// baseline (speedup 1.0000x reference)
#include <cuda_runtime.h>
#include <cstdint>

typedef unsigned long long U64;

__device__ __forceinline__ U64 pack2(float x) {
    U64 r; asm("mov.b64 %0, {%1, %1};" : "=l"(r) : "f"(x)); return r;
}
__device__ __forceinline__ void fma2(U64 &acc, U64 a, U64 b) {
    asm("fma.rn.f32x2 %0, %1, %2, %0;" : "+l"(acc) : "l"(a), "l"(b));
}

#define B_    256
#define T_    1024
#define F_    128
#define UU    64
#define NPRE  320   // P cols: [Emu_x(64) | Elv_x(64) | Wg_x(192)]
#define NW1   512   // W1 cols: [hp(64) pmu(64) plv(64) qmu_h(64) qlv_h(64) mh(192)]

__device__ float g_Wc[F_ * NPRE];          // W_in @ [Emu_top | Elv_top | Wg_top]
__device__ float g_W1[UU * NW1];           // [S | S@Pmu | S@Plv | S@Emu_bot | S@Elv_bot | S@R]
__device__ float g_P[B_ * T_ * NPRE];      // precomputed input projections (335 MB)

// ---------------------------------------------------------------------------
// Prep kernel A: g_Wc = W_in (128x128) @ [Emu[:128] | Elv[:128] | Wg[:128]]
// ---------------------------------------------------------------------------
__global__ void k_prep_wc(const float* __restrict__ Win,
                          const float* __restrict__ Emu,
                          const float* __restrict__ Elv,
                          const float* __restrict__ Wg) {
    int r = blockIdx.x;      // 0..127
    int c = threadIdx.x;     // 0..319
    float s = 0.f;
    if (c < 64) {
        for (int k = 0; k < F_; k++) s += Win[r*F_ + k] * Emu[k*64 + c];
    } else if (c < 128) {
        int j = c - 64;
        for (int k = 0; k < F_; k++) s += Win[r*F_ + k] * Elv[k*64 + j];
    } else {
        int j = c - 128;
        for (int k = 0; k < F_; k++) s += Win[r*F_ + k] * Wg[k*192 + j];
    }
    g_Wc[r*NPRE + c] = s;
}

// ---------------------------------------------------------------------------
// Prep kernel B: g_W1 = [S | S@Pmu | S@Plv | S@Emu_bot | S@Elv_bot | S@R]
// ---------------------------------------------------------------------------
__global__ void k_prep_w1(const float* __restrict__ S,
                          const float* __restrict__ Pmu,
                          const float* __restrict__ Plv,
                          const float* __restrict__ Emu,
                          const float* __restrict__ Elv,
                          const float* __restrict__ R) {
    int r = blockIdx.x;      // 0..63
    int c = threadIdx.x;     // 0..511
    float v;
    if (c < 64) {
        v = S[r*64 + c];
    } else {
        int j = c - 64;
        float s = 0.f;
        if (j < 64)       { for (int k = 0; k < 64; k++) s += S[r*64+k] * Pmu[k*64 + j]; }
        else if (j < 128) { int jj = j-64;  for (int k = 0; k < 64; k++) s += S[r*64+k] * Plv[k*64 + jj]; }
        else if (j < 192) { int jj = j-128; for (int k = 0; k < 64; k++) s += S[r*64+k] * Emu[(128+k)*64 + jj]; }
        else if (j < 256) { int jj = j-192; for (int k = 0; k < 64; k++) s += S[r*64+k] * Elv[(128+k)*64 + jj]; }
        else              { int jj = j-256; for (int k = 0; k < 64; k++) s += S[r*64+k] * R[k*192 + jj]; }
        v = s;
    }
    g_W1[r*NW1 + c] = v;
}

// ---------------------------------------------------------------------------
// GEMM: g_P[m][n] = sum_k x[m][k] * g_Wc[k][n]   (M=262144, K=128, N=320)
// fp32, f32x2-packed FMAs. BM=128, BN=64, full K in smem, 256 threads,
// per-thread 4 rows x 8 cols micro-tile.
// ---------------------------------------------------------------------------
#define GBM 128
#define GBN 64
#define SA_STRIDE 132   // 128 + 4 pad: conflict-controlled column reads, keeps 16B align
#define GEMM_SMEM_BYTES ((128*SA_STRIDE + 128*GBN) * 4)

__global__ void __launch_bounds__(256, 2) k_gemm_p(const float* __restrict__ x) {
    extern __shared__ float sm[];
    float* sA = sm;                       // [128][SA_STRIDE]
    float* sB = sm + 128 * SA_STRIDE;     // [128][64]
    int tid = threadIdx.x;
    int mb = blockIdx.x * GBM;
    int nb = blockIdx.y * GBN;

    // fill A (row-major, padded stride), coalesced gmem float4 loads
    for (int i = tid; i < 128 * 32; i += 256) {
        int r = i >> 5, c4 = (i & 31) << 2;
        float4 v = *(const float4*)(x + (mb + r) * F_ + c4);
        *(float4*)(sA + r * SA_STRIDE + c4) = v;
    }
    // fill B slice
    for (int i = tid; i < 128 * 16; i += 256) {
        int k = i >> 4, c4 = (i & 15) << 2;
        *(float4*)(sB + k * GBN + c4) = *(const float4*)(g_Wc + k * NPRE + nb + c4);
    }
    __syncthreads();

    int cg = tid & 7, rg = tid >> 3;
    int c0 = cg << 3, r0 = rg << 2;

    U64 acc[4][4];
#pragma unroll
    for (int i = 0; i < 4; i++)
#pragma unroll
        for (int j = 0; j < 4; j++) acc[i][j] = 0ull;

#pragma unroll 4
    for (int k = 0; k < 128; k++) {
        float a0 = sA[(r0+0)*SA_STRIDE + k];
        float a1 = sA[(r0+1)*SA_STRIDE + k];
        float a2 = sA[(r0+2)*SA_STRIDE + k];
        float a3 = sA[(r0+3)*SA_STRIDE + k];
        ulonglong2 b01 = *(const ulonglong2*)(sB + k*GBN + c0);
        ulonglong2 b23 = *(const ulonglong2*)(sB + k*GBN + c0 + 4);
        U64 p0 = pack2(a0), p1 = pack2(a1), p2 = pack2(a2), p3 = pack2(a3);
        fma2(acc[0][0], p0, b01.x); fma2(acc[0][1], p0, b01.y);
        fma2(acc[0][2], p0, b23.x); fma2(acc[0][3], p0, b23.y);
        fma2(acc[1][0], p1, b01.x); fma2(acc[1][1], p1, b01.y);
        fma2(acc[1][2], p1, b23.x); fma2(acc[1][3], p1, b23.y);
        fma2(acc[2][0], p2, b01.x); fma2(acc[2][1], p2, b01.y);
        fma2(acc[2][2], p2, b23.x); fma2(acc[2][3], p2, b23.y);
        fma2(acc[3][0], p3, b01.x); fma2(acc[3][1], p3, b01.y);
        fma2(acc[3][2], p3, b23.x); fma2(acc[3][3], p3, b23.y);
    }

#pragma unroll
    for (int i = 0; i < 4; i++) {
        float* dst = g_P + (mb + r0 + i) * NPRE + nb + c0;
        ulonglong2 v0; v0.x = acc[i][0]; v0.y = acc[i][1];
        *(ulonglong2*)dst = v0;
        ulonglong2 v1; v1.x = acc[i][2]; v1.y = acc[i][3];
        *(ulonglong2*)(dst + 4) = v1;
    }
}

// ---------------------------------------------------------------------------
// Recurrent kernel: 128 CTAs x 2 batch rows, 256 threads, weights in smem.
// Per step:  Y = h @ W1 (512 cols)  ->  z/outputs  ->  G = z @ W2 (192 cols)
//            -> GRU gates -> h_new.  4 __syncthreads per step.
// ---------------------------------------------------------------------------
#define RNN_SMEM_FLOATS (32768 + 12288 + 192 + 192 + 128 + 1024 + 640 + 128 + 768)
#define RNN_SMEM_BYTES  (RNN_SMEM_FLOATS * 4)

__global__ void __launch_bounds__(256, 1) k_rnn(const float* __restrict__ gbias,
                                                const float* __restrict__ gruk,
                                                float* __restrict__ out) {
    extern __shared__ float sm[];
    float* sW1 = sm;                  // [64][512]
    float* sW2 = sW1 + 64 * 512;      // [64][192]  (= gru_kernel rows 128..191)
    float* sB0 = sW2 + 64 * 192;      // [192]
    float* sB1 = sB0 + 192;           // [192]
    float* sH  = sB1 + 192;           // [2][64]
    float* sY  = sH + 128;            // [2][512]
    float* sP  = sY + 1024;           // [2][320]
    float* sZ  = sP + 640;            // [2][64]
    float* sG  = sZ + 128;            // [4][192]  (kh*2 + r)

    int tid = threadIdx.x;
    int b0  = blockIdx.x * 2;

    // load weights/bias to smem once
    for (int i = tid; i < (64*512)/4; i += 256)
        *(float4*)(sW1 + i*4) = *(const float4*)(g_W1 + i*4);
    for (int i = tid; i < (64*192)/4; i += 256)
        *(float4*)(sW2 + i*4) = *(const float4*)(gruk + 128*192 + i*4);
    if (tid < 96)
        *(float4*)(sB0 + tid*4) = *(const float4*)(gbias + tid*4);  // fills sB0 then sB1
    if (tid < 128) sH[tid] = 0.f;

    // per-thread constant mappings
    int r1 = tid >> 7;                 // M1: row
    int c1 = (tid & 127) << 2;         // M1: 4-col base in [0,512)
    int kh  = (tid < 192) ? (tid / 96) : 0;   // M2: K-half
    int rm  = (tid < 192) ? (tid - kh*96) : 0;
    int r2  = rm / 48;                 // M2: row
    int c2  = (rm - r2*48) << 2;       // M2: 4-col base in [0,192)
    int k20 = kh << 5;
    int re = tid >> 6;                 // elementwise/gate: row (tid<128)
    int ue = tid & 63;                 //                  unit
    int rp = (tid < 160) ? (tid / 80) : 0;     // P load: row
    int jp = (tid < 160) ? ((tid - rp*80) << 2) : 0;

    const int SEQ = B_ * T_ * UU;
    __syncthreads();

    for (int t = 0; t < T_; t++) {
        // prefetch this step's P rows (lands during M1)
        float4 pv;
        if (tid < 160)
            pv = *(const float4*)(g_P + ((b0 + rp) * T_ + t) * NPRE + jp);

        // M1: Y[r1][c1..c1+3] = sum_k h[r1][k] * W1[k][c1..c1+3]
        U64 a0 = 0ull, a1 = 0ull;
        const float* hr = sH + (r1 << 6);
        const float* w1 = sW1 + c1;
#pragma unroll
        for (int k = 0; k < 64; k += 4) {
            float4 hv = *(const float4*)(hr + k);
            { U64 p = pack2(hv.x); ulonglong2 b = *(const ulonglong2*)(w1 + (k+0)*NW1); fma2(a0,p,b.x); fma2(a1,p,b.y); }
            { U64 p = pack2(hv.y); ulonglong2 b = *(const ulonglong2*)(w1 + (k+1)*NW1); fma2(a0,p,b.x); fma2(a1,p,b.y); }
            { U64 p = pack2(hv.z); ulonglong2 b = *(const ulonglong2*)(w1 + (k+2)*NW1); fma2(a0,p,b.x); fma2(a1,p,b.y); }
            { U64 p = pack2(hv.w); ulonglong2 b = *(const ulonglong2*)(w1 + (k+3)*NW1); fma2(a0,p,b.x); fma2(a1,p,b.y); }
        }
        { ulonglong2 v; v.x = a0; v.y = a1; *(ulonglong2*)(sY + (r1 << 9) + c1) = v; }
        if (tid < 160) *(float4*)(sP + rp*320 + jp) = pv;
        __syncthreads();

        // elementwise 1: z, outputs
        if (tid < 128) {
            const float* Yr = sY + (re << 9);
            const float* Pr = sP + re * 320;
            float pmu = Yr[64 + ue];
            float plv = Yr[128 + ue];
            float qmu = Yr[192 + ue] + Pr[ue];
            float qlv = Yr[256 + ue] + Pr[64 + ue];
            float z   = 0.5f * __expf(qlv) + qmu;
            sZ[(re << 6) + ue] = z;
            int base = ((b0 + re) * T_ + t) * UU + ue;
            out[base]         = z;
            out[base + SEQ]   = qmu;
            out[base + 2*SEQ] = pmu;
            out[base + 3*SEQ] = qlv;
            out[base + 4*SEQ] = plv;
        }
        __syncthreads();

        // M2: G_partial[kh][r2][c2..c2+3] = sum_{k in half} z[r2][k] * W2[k][c..]
        if (tid < 192) {
            U64 g0 = 0ull, g1 = 0ull;
            const float* zr = sZ + (r2 << 6);
            const float* w2 = sW2 + c2;
#pragma unroll
            for (int k = k20; k < k20 + 32; k += 4) {
                float4 zv = *(const float4*)(zr + k);
                { U64 p = pack2(zv.x); ulonglong2 b = *(const ulonglong2*)(w2 + (k+0)*192); fma2(g0,p,b.x); fma2(g1,p,b.y); }
                { U64 p = pack2(zv.y); ulonglong2 b = *(const ulonglong2*)(w2 + (k+1)*192); fma2(g0,p,b.x); fma2(g1,p,b.y); }
                { U64 p = pack2(zv.z); ulonglong2 b = *(const ulonglong2*)(w2 + (k+2)*192); fma2(g0,p,b.x); fma2(g1,p,b.y); }
                { U64 p = pack2(zv.w); ulonglong2 b = *(const ulonglong2*)(w2 + (k+3)*192); fma2(g0,p,b.x); fma2(g1,p,b.y); }
            }
            ulonglong2 v; v.x = g0; v.y = g1;
            *(ulonglong2*)(sG + ((kh << 1) + r2) * 192 + c2) = v;
        }
        __syncthreads();

        // gates -> h_new
        if (tid < 128) {
            const float* Yr = sY + (re << 9);
            const float* Pr = sP + re * 320;
            const float* Ga = sG + re * 192;
            const float* Gb = sG + (2 + re) * 192;
            float hp  = Yr[ue];
            float mxz = Pr[128 + ue] + Ga[ue]       + Gb[ue]       + sB0[ue];
            float mxr = Pr[192 + ue] + Ga[64 + ue]  + Gb[64 + ue]  + sB0[64 + ue];
            float mxh = Pr[256 + ue] + Ga[128 + ue] + Gb[128 + ue] + sB0[128 + ue];
            float mhz = Yr[320 + ue] + sB1[ue];
            float mhr = Yr[384 + ue] + sB1[64 + ue];
            float mhh = Yr[448 + ue] + sB1[128 + ue];
            float zt = 1.f / (1.f + __expf(-(mxz + mhz)));
            float rt = 1.f / (1.f + __expf(-(mxr + mhr)));
            float hh = tanhf(mxh + rt * mhh);
            sH[(re << 6) + ue] = zt * hp + (1.f - zt) * hh;
        }
        __syncthreads();
    }
}

// ---------------------------------------------------------------------------
extern "C" void kernel_launch(void* const* d_in, const int* in_sizes, int n_in,
                              void* d_out, int out_size) {
    const float* x   = (const float*)d_in[0];   // (256,1024,128)
    const float* Win = (const float*)d_in[1];   // (128,128)
    const float* S   = (const float*)d_in[2];   // (64,64)
    const float* Emu = (const float*)d_in[3];   // (192,64)
    const float* Elv = (const float*)d_in[4];   // (192,64)
    const float* Pmu = (const float*)d_in[5];   // (64,64)
    const float* Plv = (const float*)d_in[6];   // (64,64)
    const float* Wg  = (const float*)d_in[7];   // (192,192)
    const float* R   = (const float*)d_in[8];   // (64,192)
    const float* gb  = (const float*)d_in[9];   // (2,192)

    cudaFuncSetAttribute(k_gemm_p, cudaFuncAttributeMaxDynamicSharedMemorySize, GEMM_SMEM_BYTES);
    cudaFuncSetAttribute(k_rnn,    cudaFuncAttributeMaxDynamicSharedMemorySize, RNN_SMEM_BYTES);

    k_prep_wc<<<128, 320>>>(Win, Emu, Elv, Wg);
    k_prep_w1<<<64, 512>>>(S, Pmu, Plv, Emu, Elv, R);

    dim3 gg(2048, 5);
    k_gemm_p<<<gg, 256, GEMM_SMEM_BYTES>>>(x);

    k_rnn<<<128, 256, RNN_SMEM_BYTES>>>(gb, Wg, (float*)d_out);
}

// round 2
// speedup vs baseline: 1.1755x; 1.1755x over previous
#include <cuda_runtime.h>
#include <cstdint>

typedef unsigned long long U64;

__device__ __forceinline__ U64 pack2(float x) {
    U64 r; asm("mov.b64 %0, {%1, %1};" : "=l"(r) : "f"(x)); return r;
}
__device__ __forceinline__ void fma2(U64 &acc, U64 a, U64 b) {
    asm("fma.rn.f32x2 %0, %1, %2, %0;" : "+l"(acc) : "l"(a), "l"(b));
}
__device__ __forceinline__ float sigmoid_f(float x) {
    return 1.f / (1.f + __expf(-x));
}
__device__ __forceinline__ float tanh_exp(float x) {
    // tanh(x) = 1 - 2/(exp(2x)+1); exp via ex2.approx (rel err ~1e-7 pre-div)
    float e = __expf(2.f * x);
    return 1.f - __fdividef(2.f, e + 1.f);
}

#define B_    256
#define T_    1024
#define F_    128
#define UU    64
#define NPRE  320   // P cols: [Emu_x(64) | Elv_x(64) | Wg_x(192)]
#define NW1   512   // W1 cols: [hp(64) pmu(64) plv(64) qmu_h(64) qlv_h(64) mh(192)]

__device__ float g_Wc[F_ * NPRE];          // W_in @ [Emu_top | Elv_top | Wg_top]
__device__ float g_W1[UU * NW1];           // [S | S@Pmu | S@Plv | S@Emu_bot | S@Elv_bot | S@R]
__device__ float g_P[B_ * T_ * NPRE];      // precomputed input projections

// ---------------------------------------------------------------------------
// Prep kernel A: g_Wc = W_in (128x128) @ [Emu[:128] | Elv[:128] | Wg[:128]]
// ---------------------------------------------------------------------------
__global__ void k_prep_wc(const float* __restrict__ Win,
                          const float* __restrict__ Emu,
                          const float* __restrict__ Elv,
                          const float* __restrict__ Wg) {
    int r = blockIdx.x;      // 0..127
    int c = threadIdx.x;     // 0..319
    float s = 0.f;
    if (c < 64) {
        for (int k = 0; k < F_; k++) s += Win[r*F_ + k] * Emu[k*64 + c];
    } else if (c < 128) {
        int j = c - 64;
        for (int k = 0; k < F_; k++) s += Win[r*F_ + k] * Elv[k*64 + j];
    } else {
        int j = c - 128;
        for (int k = 0; k < F_; k++) s += Win[r*F_ + k] * Wg[k*192 + j];
    }
    g_Wc[r*NPRE + c] = s;
}

// ---------------------------------------------------------------------------
// Prep kernel B: g_W1 = [S | S@Pmu | S@Plv | S@Emu_bot | S@Elv_bot | S@R]
// ---------------------------------------------------------------------------
__global__ void k_prep_w1(const float* __restrict__ S,
                          const float* __restrict__ Pmu,
                          const float* __restrict__ Plv,
                          const float* __restrict__ Emu,
                          const float* __restrict__ Elv,
                          const float* __restrict__ R) {
    int r = blockIdx.x;      // 0..63
    int c = threadIdx.x;     // 0..511
    float v;
    if (c < 64) {
        v = S[r*64 + c];
    } else {
        int j = c - 64;
        float s = 0.f;
        if (j < 64)       { for (int k = 0; k < 64; k++) s += S[r*64+k] * Pmu[k*64 + j]; }
        else if (j < 128) { int jj = j-64;  for (int k = 0; k < 64; k++) s += S[r*64+k] * Plv[k*64 + jj]; }
        else if (j < 192) { int jj = j-128; for (int k = 0; k < 64; k++) s += S[r*64+k] * Emu[(128+k)*64 + jj]; }
        else if (j < 256) { int jj = j-192; for (int k = 0; k < 64; k++) s += S[r*64+k] * Elv[(128+k)*64 + jj]; }
        else              { int jj = j-256; for (int k = 0; k < 64; k++) s += S[r*64+k] * R[k*192 + jj]; }
        v = s;
    }
    g_W1[r*NW1 + c] = v;
}

// ---------------------------------------------------------------------------
// GEMM: g_P[m][n] = sum_k x[m][k] * g_Wc[k][n]   (M=262144, K=128, N=320)
// ---------------------------------------------------------------------------
#define GBM 128
#define GBN 64
#define SA_STRIDE 132
#define GEMM_SMEM_BYTES ((128*SA_STRIDE + 128*GBN) * 4)

__global__ void __launch_bounds__(256, 2) k_gemm_p(const float* __restrict__ x) {
    extern __shared__ float sm[];
    float* sA = sm;                       // [128][SA_STRIDE]
    float* sB = sm + 128 * SA_STRIDE;     // [128][64]
    int tid = threadIdx.x;
    int mb = blockIdx.x * GBM;
    int nb = blockIdx.y * GBN;

    for (int i = tid; i < 128 * 32; i += 256) {
        int r = i >> 5, c4 = (i & 31) << 2;
        float4 v = *(const float4*)(x + (mb + r) * F_ + c4);
        *(float4*)(sA + r * SA_STRIDE + c4) = v;
    }
    for (int i = tid; i < 128 * 16; i += 256) {
        int k = i >> 4, c4 = (i & 15) << 2;
        *(float4*)(sB + k * GBN + c4) = *(const float4*)(g_Wc + k * NPRE + nb + c4);
    }
    __syncthreads();

    int cg = tid & 7, rg = tid >> 3;
    int c0 = cg << 3, r0 = rg << 2;

    U64 acc[4][4];
#pragma unroll
    for (int i = 0; i < 4; i++)
#pragma unroll
        for (int j = 0; j < 4; j++) acc[i][j] = 0ull;

#pragma unroll 4
    for (int k = 0; k < 128; k++) {
        float a0 = sA[(r0+0)*SA_STRIDE + k];
        float a1 = sA[(r0+1)*SA_STRIDE + k];
        float a2 = sA[(r0+2)*SA_STRIDE + k];
        float a3 = sA[(r0+3)*SA_STRIDE + k];
        ulonglong2 b01 = *(const ulonglong2*)(sB + k*GBN + c0);
        ulonglong2 b23 = *(const ulonglong2*)(sB + k*GBN + c0 + 4);
        U64 p0 = pack2(a0), p1 = pack2(a1), p2 = pack2(a2), p3 = pack2(a3);
        fma2(acc[0][0], p0, b01.x); fma2(acc[0][1], p0, b01.y);
        fma2(acc[0][2], p0, b23.x); fma2(acc[0][3], p0, b23.y);
        fma2(acc[1][0], p1, b01.x); fma2(acc[1][1], p1, b01.y);
        fma2(acc[1][2], p1, b23.x); fma2(acc[1][3], p1, b23.y);
        fma2(acc[2][0], p2, b01.x); fma2(acc[2][1], p2, b01.y);
        fma2(acc[2][2], p2, b23.x); fma2(acc[2][3], p2, b23.y);
        fma2(acc[3][0], p3, b01.x); fma2(acc[3][1], p3, b01.y);
        fma2(acc[3][2], p3, b23.x); fma2(acc[3][3], p3, b23.y);
    }

#pragma unroll
    for (int i = 0; i < 4; i++) {
        float* dst = g_P + (mb + r0 + i) * NPRE + nb + c0;
        ulonglong2 v0; v0.x = acc[i][0]; v0.y = acc[i][1];
        *(ulonglong2*)dst = v0;
        ulonglong2 v1; v1.x = acc[i][2]; v1.y = acc[i][3];
        *(ulonglong2*)(dst + 4) = v1;
    }
}

// ---------------------------------------------------------------------------
// Recurrent kernel, v2: W1 register-resident (each thread owns 1 col-pair of
// all 64 K as packed f32x2), h broadcast from smem as pre-dupped {h,h} u64.
// W2 stays in smem, read row-amortized + K-split (each weight read once).
// 128 CTAs x 2 batch rows x 256 threads.
// ---------------------------------------------------------------------------
// smem float offsets
#define OFF_W2  0              // [64][192]
#define OFF_B0  12288          // [192]
#define OFF_B1  12480          // [192]
#define OFF_Y   12672          // [2][512]
#define OFF_P   13696          // [2][320]
#define OFF_G   14336          // [4][192]  (half*2 + row)
#define OFF_H2  15104          // U64 [2][64] dup'd h  (16B aligned: 15104*4=60416)
#define OFF_Z2  15360          // U64 [2][64] dup'd z
#define RNN_SMEM_FLOATS 15616
#define RNN_SMEM_BYTES  (RNN_SMEM_FLOATS * 4)

__global__ void __launch_bounds__(256, 1) k_rnn(const float* __restrict__ gbias,
                                                const float* __restrict__ gruk,
                                                float* __restrict__ out) {
    extern __shared__ float sm[];
    float* sW2 = sm + OFF_W2;
    float* sB0 = sm + OFF_B0;
    float* sB1 = sm + OFF_B1;
    float* sY  = sm + OFF_Y;
    float* sP  = sm + OFF_P;
    float* sG  = sm + OFF_G;
    U64*   sH2 = (U64*)(sm + OFF_H2);   // [2][64]
    U64*   sZ2 = (U64*)(sm + OFF_Z2);   // [2][64]

    int tid = threadIdx.x;
    int b0  = blockIdx.x * 2;

    // --- load W2 (gru_kernel rows 128..191), biases to smem; zero h ---
    for (int i = tid; i < (64*192)/4; i += 256)
        *(float4*)(sW2 + i*4) = *(const float4*)(gruk + 128*192 + i*4);
    if (tid < 96)
        *(float4*)(sB0 + tid*4) = *(const float4*)(gbias + tid*4);  // fills B0 then B1
    if (tid < 128) sH2[tid] = 0ull;

    // --- W1 into registers: this thread owns cols (2*tid, 2*tid+1), all 64 k ---
    const int c = tid << 1;
    U64 w1reg[64];
#pragma unroll
    for (int k = 0; k < 64; k++)
        w1reg[k] = *(const U64*)(g_W1 + k * NW1 + c);

    // per-thread constant mappings
    int re = tid >> 6;                       // eltwise row (tid<128)
    int ue = tid & 63;                       // eltwise unit
    int hf = (tid < 96) ? 0 : 1;             // M2 K-half
    int j2 = (tid < 96) ? tid : (tid - 96);  // M2 col-pair index (tid<192)
    int kb = hf << 5;                        // M2 k base
    int rp = (tid < 160) ? (tid / 80) : 0;   // P-prefetch row
    int jp = (tid < 160) ? ((tid - rp*80) << 2) : 0;

    const int SEQ = B_ * T_ * UU;
    __syncthreads();

#pragma unroll 1
    for (int t = 0; t < T_; t++) {
        // prefetch this step's P rows (lands during M1)
        float4 pv;
        if (tid < 160)
            pv = *(const float4*)(g_P + ((b0 + rp) * T_ + t) * NPRE + jp);

        // ---- M1: Y[r][c..c+1] = sum_k h[r][k] * W1[k][c..c+1] (weights in regs)
        U64 a0 = 0ull, a1 = 0ull;
#pragma unroll
        for (int k = 0; k < 64; k += 2) {
            ulonglong2 h0 = *(const ulonglong2*)(sH2 + k);        // row0 {h,h} x2
            ulonglong2 h1 = *(const ulonglong2*)(sH2 + 64 + k);   // row1
            fma2(a0, h0.x, w1reg[k]);   fma2(a1, h1.x, w1reg[k]);
            fma2(a0, h0.y, w1reg[k+1]); fma2(a1, h1.y, w1reg[k+1]);
        }
        *(U64*)(sY + c)       = a0;
        *(U64*)(sY + 512 + c) = a1;
        if (tid < 160) *(float4*)(sP + rp*320 + jp) = pv;
        __syncthreads();

        // ---- elt1: z + outputs
        if (tid < 128) {
            const float* Yr = sY + (re << 9);
            const float* Pr = sP + re * 320;
            float pmu = Yr[64 + ue];
            float plv = Yr[128 + ue];
            float qmu = Yr[192 + ue] + Pr[ue];
            float qlv = Yr[256 + ue] + Pr[64 + ue];
            float z   = 0.5f * __expf(qlv) + qmu;
            sZ2[(re << 6) + ue] = pack2(z);
            int base = ((b0 + re) * T_ + t) * UU + ue;
            out[base]         = z;
            out[base + SEQ]   = qmu;
            out[base + 2*SEQ] = pmu;
            out[base + 3*SEQ] = qlv;
            out[base + 4*SEQ] = plv;
        }
        __syncthreads();

        // ---- M2: G_half[hf][r][2j..2j+1] = sum_{k in half} z[r][k]*W2[k][..]
        if (tid < 192) {
            U64 g0 = 0ull, g1 = 0ull;
            const float* w2 = sW2 + (j2 << 1);
#pragma unroll
            for (int kk = 0; kk < 32; kk += 2) {
                int k = kb + kk;
                ulonglong2 z0 = *(const ulonglong2*)(sZ2 + k);
                ulonglong2 z1 = *(const ulonglong2*)(sZ2 + 64 + k);
                U64 wa = *(const U64*)(w2 + k * 192);
                U64 wb = *(const U64*)(w2 + (k+1) * 192);
                fma2(g0, z0.x, wa); fma2(g1, z1.x, wa);
                fma2(g0, z0.y, wb); fma2(g1, z1.y, wb);
            }
            *(U64*)(sG + ((hf << 1) + 0) * 192 + (j2 << 1)) = g0;
            *(U64*)(sG + ((hf << 1) + 1) * 192 + (j2 << 1)) = g1;
        }
        __syncthreads();

        // ---- elt2: gates -> h_new (dup-packed into sH2)
        if (tid < 128) {
            const float* Yr = sY + (re << 9);
            const float* Pr = sP + re * 320;
            const float* Ga = sG + re * 192;
            const float* Gb = sG + (2 + re) * 192;
            float hp  = Yr[ue];
            float mxz = Pr[128 + ue] + Ga[ue]       + Gb[ue]       + sB0[ue];
            float mxr = Pr[192 + ue] + Ga[64 + ue]  + Gb[64 + ue]  + sB0[64 + ue];
            float mxh = Pr[256 + ue] + Ga[128 + ue] + Gb[128 + ue] + sB0[128 + ue];
            float mhz = Yr[320 + ue] + sB1[ue];
            float mhr = Yr[384 + ue] + sB1[64 + ue];
            float mhh = Yr[448 + ue] + sB1[128 + ue];
            float zt = sigmoid_f(mxz + mhz);
            float rt = sigmoid_f(mxr + mhr);
            float hh = tanh_exp(mxh + rt * mhh);
            float hn = zt * hp + (1.f - zt) * hh;
            sH2[(re << 6) + ue] = pack2(hn);
        }
        __syncthreads();
    }
}

// ---------------------------------------------------------------------------
extern "C" void kernel_launch(void* const* d_in, const int* in_sizes, int n_in,
                              void* d_out, int out_size) {
    const float* x   = (const float*)d_in[0];   // (256,1024,128)
    const float* Win = (const float*)d_in[1];   // (128,128)
    const float* S   = (const float*)d_in[2];   // (64,64)
    const float* Emu = (const float*)d_in[3];   // (192,64)
    const float* Elv = (const float*)d_in[4];   // (192,64)
    const float* Pmu = (const float*)d_in[5];   // (64,64)
    const float* Plv = (const float*)d_in[6];   // (64,64)
    const float* Wg  = (const float*)d_in[7];   // (192,192)
    const float* R   = (const float*)d_in[8];   // (64,192)
    const float* gb  = (const float*)d_in[9];   // (2,192)

    cudaFuncSetAttribute(k_gemm_p, cudaFuncAttributeMaxDynamicSharedMemorySize, GEMM_SMEM_BYTES);
    cudaFuncSetAttribute(k_rnn,    cudaFuncAttributeMaxDynamicSharedMemorySize, RNN_SMEM_BYTES);

    k_prep_wc<<<128, 320>>>(Win, Emu, Elv, Wg);
    k_prep_w1<<<64, 512>>>(S, Pmu, Plv, Emu, Elv, R);

    dim3 gg(2048, 5);
    k_gemm_p<<<gg, 256, GEMM_SMEM_BYTES>>>(x);

    k_rnn<<<128, 256, RNN_SMEM_BYTES>>>(gb, Wg, (float*)d_out);
}